// round 1
// baseline (speedup 1.0000x reference)
#include <cuda_runtime.h>
#include <math.h>

#define Bb   4
#define Tt   2048
#define Dd   1024
#define Hh   4
#define DKk  256
#define DVv  512
#define KDIM 1024
#define VDIM 2048
#define FFND 4096
#define NROWS (Bb*Tt)   /* 8192 */

// ---------------- scratch (static __device__ — no allocations allowed) ----------------
__device__ float g_normed[NROWS*Dd];
__device__ float g_xq[NROWS*KDIM];
__device__ float g_xk[NROWS*KDIM];
__device__ float g_xv[NROWS*VDIM];
__device__ float g_q[NROWS*KDIM];
__device__ float g_k[NROWS*KDIM];
__device__ float g_v[NROWS*VDIM];
__device__ float g_gate[NROWS*VDIM];
__device__ float g_gg[NROWS*Hh];
__device__ float g_bb[NROWS*Hh];
__device__ float g_o[NROWS*VDIM];
__device__ float g_x2[NROWS*Dd];
__device__ float g_hbuf[NROWS*Dd];
__device__ float g_ffn1[NROWS*FFND];

// ---------------- helpers ----------------
__device__ __forceinline__ float sigmoidf_(float x) { return 1.0f / (1.0f + expf(-x)); }
__device__ __forceinline__ float siluf_(float x)    { return x * sigmoidf_(x); }
__device__ __forceinline__ float geluf_(float x)    { return 0.5f * x * (1.0f + erff(x * 0.70710678118654752f)); }
__device__ __forceinline__ float softplusf_(float x){ return (x > 20.0f) ? x : log1pf(expf(x)); }

// ---------------- LayerNorm: one block per row (D=1024), 256 threads ----------------
__global__ void ln_kernel(const float* __restrict__ x, const float* __restrict__ w,
                          const float* __restrict__ b, float* __restrict__ out) {
    int row = blockIdx.x;
    const float* xr = x + (size_t)row * Dd;
    float s1 = 0.f, s2 = 0.f;
    float vals[4];
    #pragma unroll
    for (int i = 0; i < 4; i++) {
        float v = xr[threadIdx.x + i * 256];
        vals[i] = v; s1 += v; s2 += v * v;
    }
    __shared__ float sh[2][8];
    int lane = threadIdx.x & 31, wid = threadIdx.x >> 5;
    #pragma unroll
    for (int off = 16; off > 0; off >>= 1) {
        s1 += __shfl_xor_sync(0xffffffffu, s1, off);
        s2 += __shfl_xor_sync(0xffffffffu, s2, off);
    }
    if (lane == 0) { sh[0][wid] = s1; sh[1][wid] = s2; }
    __syncthreads();
    if (threadIdx.x == 0) {
        float a = 0.f, c = 0.f;
        #pragma unroll
        for (int i = 0; i < 8; i++) { a += sh[0][i]; c += sh[1][i]; }
        sh[0][0] = a; sh[1][0] = c;
    }
    __syncthreads();
    float mean = sh[0][0] * (1.0f / Dd);
    float var  = sh[1][0] * (1.0f / Dd) - mean * mean;
    float inv  = rsqrtf(var + 1e-5f);
    #pragma unroll
    for (int i = 0; i < 4; i++) {
        int c = threadIdx.x + i * 256;
        out[(size_t)row * Dd + c] = (vals[i] - mean) * inv * w[c] + b[c];
    }
}

// ---------------- SGEMM 128x128x8, fp32, row-major. EPI: 0 none,1 bias,2 bias+gelu,3 res,4 bias+res
template<int EPI>
__global__ void __launch_bounds__(256)
sgemm_kernel(const float* __restrict__ A, const float* __restrict__ Bm, float* __restrict__ C,
             int M, int N, int K, const float* __restrict__ bias, const float* __restrict__ res) {
    __shared__ float As[8][128];
    __shared__ float Bs[8][128];
    int tid = threadIdx.x;
    int bm = blockIdx.y * 128, bn = blockIdx.x * 128;
    int tx = tid & 15, ty = tid >> 4;

    float acc[8][8];
    #pragma unroll
    for (int i = 0; i < 8; i++)
        #pragma unroll
        for (int j = 0; j < 8; j++) acc[i][j] = 0.f;

    int arow = tid >> 1, acol = (tid & 1) * 4;
    int brow = tid >> 5, bcol = (tid & 31) * 4;
    const float* Aptr = A + (size_t)(bm + arow) * K + acol;
    const float* Bptr = Bm + (size_t)brow * N + bn + bcol;

    for (int k0 = 0; k0 < K; k0 += 8) {
        float4 av = *(const float4*)(Aptr + k0);
        float4 bv = *(const float4*)(Bptr + (size_t)k0 * N);
        __syncthreads();
        As[acol + 0][arow] = av.x;
        As[acol + 1][arow] = av.y;
        As[acol + 2][arow] = av.z;
        As[acol + 3][arow] = av.w;
        *(float4*)&Bs[brow][bcol] = bv;
        __syncthreads();
        #pragma unroll
        for (int kk = 0; kk < 8; kk++) {
            float4 a0 = *(const float4*)&As[kk][ty * 8];
            float4 a1 = *(const float4*)&As[kk][ty * 8 + 4];
            float4 b0 = *(const float4*)&Bs[kk][tx * 8];
            float4 b1 = *(const float4*)&Bs[kk][tx * 8 + 4];
            float ar[8] = {a0.x, a0.y, a0.z, a0.w, a1.x, a1.y, a1.z, a1.w};
            float br[8] = {b0.x, b0.y, b0.z, b0.w, b1.x, b1.y, b1.z, b1.w};
            #pragma unroll
            for (int i = 0; i < 8; i++)
                #pragma unroll
                for (int j = 0; j < 8; j++) acc[i][j] += ar[i] * br[j];
        }
    }

    #pragma unroll
    for (int i = 0; i < 8; i++) {
        int row = bm + ty * 8 + i;
        #pragma unroll
        for (int jj = 0; jj < 2; jj++) {
            int col = bn + tx * 8 + jj * 4;
            float4 v;
            v.x = acc[i][jj * 4 + 0]; v.y = acc[i][jj * 4 + 1];
            v.z = acc[i][jj * 4 + 2]; v.w = acc[i][jj * 4 + 3];
            if (EPI == 1 || EPI == 2 || EPI == 4) {
                float4 bb = *(const float4*)(bias + col);
                v.x += bb.x; v.y += bb.y; v.z += bb.z; v.w += bb.w;
            }
            if (EPI == 2) { v.x = geluf_(v.x); v.y = geluf_(v.y); v.z = geluf_(v.z); v.w = geluf_(v.w); }
            if (EPI == 3 || EPI == 4) {
                float4 rr = *(const float4*)(res + (size_t)row * N + col);
                v.x += rr.x; v.y += rr.y; v.z += rr.z; v.w += rr.w;
            }
            *(float4*)(C + (size_t)row * N + col) = v;
        }
    }
}

// ---------------- g / beta: small projections (N=4 each) fused ----------------
__global__ void gbeta_kernel(const float* __restrict__ normed, const float* __restrict__ Wa,
                             const float* __restrict__ Wb, const float* __restrict__ A_log,
                             const float* __restrict__ dt_bias, float* __restrict__ g,
                             float* __restrict__ beta) {
    int row = blockIdx.x * 8 + (threadIdx.x >> 5);
    int lane = threadIdx.x & 31;
    const float* xr = normed + (size_t)row * Dd;
    float acc[8];
    #pragma unroll
    for (int j = 0; j < 8; j++) acc[j] = 0.f;
    for (int k = lane; k < Dd; k += 32) {
        float xv = xr[k];
        const float* wa = Wa + k * 4;
        const float* wb = Wb + k * 4;
        #pragma unroll
        for (int j = 0; j < 4; j++) { acc[j] += xv * wa[j]; acc[4 + j] += xv * wb[j]; }
    }
    #pragma unroll
    for (int off = 16; off > 0; off >>= 1)
        #pragma unroll
        for (int j = 0; j < 8; j++) acc[j] += __shfl_xor_sync(0xffffffffu, acc[j], off);
    if (lane < 4) {
        float xa = acc[lane] + dt_bias[lane];
        g[row * 4 + lane] = -expf(A_log[lane]) * softplusf_(xa);
        beta[row * 4 + lane] = sigmoidf_(acc[4 + lane]);
    }
}

// ---------------- causal depthwise conv (K=4) + SiLU ----------------
__global__ void conv_silu_kernel(const float* __restrict__ x, const float* __restrict__ w,
                                 float* __restrict__ y, int C, long total) {
    long idx = (long)blockIdx.x * blockDim.x + threadIdx.x;
    if (idx >= total) return;
    int c = (int)(idx % C);
    long bt = idx / C;
    int t = (int)(bt % Tt);
    long bbase = (bt / Tt) * Tt;
    const float* w4 = w + c * 4;
    float acc = 0.f;
    #pragma unroll
    for (int i = 0; i < 4; i++) {
        int tt = t - 3 + i;
        if (tt >= 0) acc += x[(bbase + tt) * C + c] * w4[i];
    }
    y[idx] = siluf_(acc);
}

// ---------------- l2norm over DK=256 (in-place), optional extra scale ----------------
__global__ void l2norm_kernel(float* __restrict__ x, float extra_scale) {
    int rowh = blockIdx.x;                 // NROWS*H
    float* p = x + (size_t)rowh * DKk;
    float v = p[threadIdx.x];
    float ss = v * v;
    __shared__ float sh[8];
    int lane = threadIdx.x & 31, wid = threadIdx.x >> 5;
    #pragma unroll
    for (int off = 16; off > 0; off >>= 1) ss += __shfl_xor_sync(0xffffffffu, ss, off);
    if (lane == 0) sh[wid] = ss;
    __syncthreads();
    if (threadIdx.x == 0) {
        float a = 0.f;
        #pragma unroll
        for (int i = 0; i < 8; i++) a += sh[i];
        sh[0] = a;
    }
    __syncthreads();
    p[threadIdx.x] = v * rsqrtf(sh[0] + 1e-6f) * extra_scale;
}

// ---------------- gated delta rule scan ----------------
// Grid: 128 CTAs = (b, h, slice of 64 DV columns). S slice lives in registers:
// thread (kb=tid&3, vi=tid>>2) holds S[kb+4*j][v0+vi] for j=0..63.
__global__ void __launch_bounds__(256)
scan_kernel(const float* __restrict__ q, const float* __restrict__ k, const float* __restrict__ v,
            const float* __restrict__ g, const float* __restrict__ beta, float* __restrict__ o) {
    int b  = blockIdx.x >> 5;
    int h  = (blockIdx.x >> 3) & 3;
    int sl = blockIdx.x & 7;
    int v0 = sl * 64;
    int tid = threadIdx.x;
    int kb = tid & 3, vi = tid >> 2;

    __shared__ float qs[256], ks[256], vs[64], sgb[2];
    float S[64];
    #pragma unroll
    for (int j = 0; j < 64; j++) S[j] = 0.f;
    float kreg[64];

    for (int t = 0; t < Tt; t++) {
        long row = (long)b * Tt + t;
        qs[tid] = q[row * KDIM + h * DKk + tid];
        ks[tid] = k[row * KDIM + h * DKk + tid];
        if (tid < 64) vs[tid] = v[row * VDIM + h * DVv + v0 + tid];
        if (tid == 0) { sgb[0] = expf(g[row * Hh + h]); sgb[1] = beta[row * Hh + h]; }
        __syncthreads();
        float eg = sgb[0], bt = sgb[1];

        float partial = 0.f;
        #pragma unroll
        for (int j = 0; j < 64; j++) {
            float kv = ks[kb + 4 * j];
            kreg[j] = kv;
            partial += kv * S[j];
        }
        partial += __shfl_xor_sync(0xffffffffu, partial, 1);
        partial += __shfl_xor_sync(0xffffffffu, partial, 2);
        float delta = (vs[vi] - eg * partial) * bt;

        float opart = 0.f;
        #pragma unroll
        for (int j = 0; j < 64; j++) {
            float sv = eg * S[j] + kreg[j] * delta;
            S[j] = sv;
            opart += qs[kb + 4 * j] * sv;
        }
        opart += __shfl_xor_sync(0xffffffffu, opart, 1);
        opart += __shfl_xor_sync(0xffffffffu, opart, 2);
        if (kb == 0) o[row * VDIM + h * DVv + v0 + vi] = opart;
        __syncthreads();
    }
}

// ---------------- gated RMSNorm over DV=512 per head + silu(gate) ----------------
__global__ void rmsgate_kernel(float* __restrict__ o, const float* __restrict__ gate,
                               const float* __restrict__ onw) {
    int rowh = blockIdx.x;                  // NROWS*H
    long row = rowh >> 2;
    int h = rowh & 3;
    float* op = o + row * VDIM + h * DVv;
    const float* gp = gate + row * VDIM + h * DVv;
    float v1 = op[threadIdx.x], v2 = op[threadIdx.x + 256];
    float ss = v1 * v1 + v2 * v2;
    __shared__ float sh[8];
    int lane = threadIdx.x & 31, wid = threadIdx.x >> 5;
    #pragma unroll
    for (int off = 16; off > 0; off >>= 1) ss += __shfl_xor_sync(0xffffffffu, ss, off);
    if (lane == 0) sh[wid] = ss;
    __syncthreads();
    if (threadIdx.x == 0) {
        float a = 0.f;
        #pragma unroll
        for (int i = 0; i < 8; i++) a += sh[i];
        sh[0] = a;
    }
    __syncthreads();
    float scale = rsqrtf(sh[0] * (1.0f / DVv) + 1e-5f);
    int c1 = threadIdx.x, c2 = threadIdx.x + 256;
    op[c1] = v1 * scale * onw[c1] * siluf_(gp[c1]);
    op[c2] = v2 * scale * onw[c2] * siluf_(gp[c2]);
}

// ---------------- launcher ----------------
extern "C" void kernel_launch(void* const* d_in, const int* in_sizes, int n_in,
                              void* d_out, int out_size) {
    const float* x        = (const float*)d_in[0];
    const float* Wq       = (const float*)d_in[1];
    const float* Wk       = (const float*)d_in[2];
    const float* Wv       = (const float*)d_in[3];
    const float* Wa       = (const float*)d_in[4];
    const float* Wb       = (const float*)d_in[5];
    const float* Wg       = (const float*)d_in[6];
    const float* conv_q_w = (const float*)d_in[7];
    const float* conv_k_w = (const float*)d_in[8];
    const float* conv_v_w = (const float*)d_in[9];
    const float* A_log    = (const float*)d_in[10];
    const float* dt_bias  = (const float*)d_in[11];
    const float* o_norm_w = (const float*)d_in[12];
    const float* Wo       = (const float*)d_in[13];
    const float* ln1_w    = (const float*)d_in[14];
    const float* ln1_b    = (const float*)d_in[15];
    const float* ln2_w    = (const float*)d_in[16];
    const float* ln2_b    = (const float*)d_in[17];
    const float* ffn_w1   = (const float*)d_in[18];
    const float* ffn_b1   = (const float*)d_in[19];
    const float* ffn_w2   = (const float*)d_in[20];
    const float* ffn_b2   = (const float*)d_in[21];
    float* out = (float*)d_out;

    float *normed, *xq, *xk, *xv, *q, *k, *v, *gate, *gg, *bb, *o, *x2, *hbuf, *ffn1;
    cudaGetSymbolAddress((void**)&normed, g_normed);
    cudaGetSymbolAddress((void**)&xq, g_xq);
    cudaGetSymbolAddress((void**)&xk, g_xk);
    cudaGetSymbolAddress((void**)&xv, g_xv);
    cudaGetSymbolAddress((void**)&q, g_q);
    cudaGetSymbolAddress((void**)&k, g_k);
    cudaGetSymbolAddress((void**)&v, g_v);
    cudaGetSymbolAddress((void**)&gate, g_gate);
    cudaGetSymbolAddress((void**)&gg, g_gg);
    cudaGetSymbolAddress((void**)&bb, g_bb);
    cudaGetSymbolAddress((void**)&o, g_o);
    cudaGetSymbolAddress((void**)&x2, g_x2);
    cudaGetSymbolAddress((void**)&hbuf, g_hbuf);
    cudaGetSymbolAddress((void**)&ffn1, g_ffn1);

    // 1. LayerNorm 1
    ln_kernel<<<NROWS, 256>>>(x, ln1_w, ln1_b, normed);

    // 2. projections
    {
        dim3 g1(KDIM / 128, NROWS / 128);
        sgemm_kernel<0><<<g1, 256>>>(normed, Wq, xq, NROWS, KDIM, Dd, nullptr, nullptr);
        sgemm_kernel<0><<<g1, 256>>>(normed, Wk, xk, NROWS, KDIM, Dd, nullptr, nullptr);
        dim3 g2(VDIM / 128, NROWS / 128);
        sgemm_kernel<0><<<g2, 256>>>(normed, Wv, xv, NROWS, VDIM, Dd, nullptr, nullptr);
        sgemm_kernel<0><<<g2, 256>>>(normed, Wg, gate, NROWS, VDIM, Dd, nullptr, nullptr);
    }
    gbeta_kernel<<<NROWS / 8, 256>>>(normed, Wa, Wb, A_log, dt_bias, gg, bb);

    // 3. conv + silu
    {
        long tq = (long)NROWS * KDIM;
        conv_silu_kernel<<<(unsigned)((tq + 255) / 256), 256>>>(xq, conv_q_w, q, KDIM, tq);
        conv_silu_kernel<<<(unsigned)((tq + 255) / 256), 256>>>(xk, conv_k_w, k, KDIM, tq);
        long tv = (long)NROWS * VDIM;
        conv_silu_kernel<<<(unsigned)((tv + 255) / 256), 256>>>(xv, conv_v_w, v, VDIM, tv);
    }

    // 4. l2norm (q gets DK^-0.5 = 1/16)
    l2norm_kernel<<<NROWS * Hh, 256>>>(q, 0.0625f);
    l2norm_kernel<<<NROWS * Hh, 256>>>(k, 1.0f);

    // 5. gated delta rule scan
    scan_kernel<<<Bb * Hh * 8, 256>>>(q, k, v, gg, bb, o);

    // 6. gated RMSNorm
    rmsgate_kernel<<<NROWS * Hh, 256>>>(o, gate, o_norm_w);

    // 7. x2 = x + o @ Wo
    {
        dim3 g1(Dd / 128, NROWS / 128);
        sgemm_kernel<3><<<g1, 256>>>(o, Wo, x2, NROWS, Dd, VDIM, nullptr, x);
    }

    // 8. LN2 + FFN
    ln_kernel<<<NROWS, 256>>>(x2, ln2_w, ln2_b, hbuf);
    {
        dim3 g1(FFND / 128, NROWS / 128);
        sgemm_kernel<2><<<g1, 256>>>(hbuf, ffn_w1, ffn1, NROWS, FFND, Dd, ffn_b1, nullptr);
        dim3 g2(Dd / 128, NROWS / 128);
        sgemm_kernel<4><<<g2, 256>>>(ffn1, ffn_w2, out, NROWS, Dd, FFND, ffn_b2, x2);
    }
}

// round 3
// speedup vs baseline: 1.6014x; 1.6014x over previous
#include <cuda_runtime.h>
#include <math.h>
#include <stdint.h>

#define Bb   4
#define Tt   2048
#define Dd   1024
#define Hh   4
#define DKk  256
#define DVv  512
#define KDIM 1024
#define VDIM 2048
#define FFND 4096
#define NROWS (Bb*Tt)   /* 8192 */

// ---------------- scratch ----------------
__device__ float g_normed[NROWS*Dd];
__device__ float g_xq[NROWS*KDIM];
__device__ float g_xk[NROWS*KDIM];
__device__ float g_xv[NROWS*VDIM];
__device__ float g_q[NROWS*KDIM];
__device__ float g_k[NROWS*KDIM];
__device__ float g_v[NROWS*VDIM];
__device__ float g_gate[NROWS*VDIM];
__device__ float g_gg[NROWS*Hh];
__device__ float g_bb[NROWS*Hh];
__device__ float g_o[NROWS*VDIM];
__device__ float g_x2[NROWS*Dd];
__device__ float g_hbuf[NROWS*Dd];
__device__ float g_ffn1[NROWS*FFND];
__device__ float g_wt[16*1024*1024];
#define WT_Q   0
#define WT_K   (1*1024*1024)
#define WT_V   (2*1024*1024)
#define WT_G   (4*1024*1024)
#define WT_O   (6*1024*1024)
#define WT_F1  (8*1024*1024)
#define WT_F2  (12*1024*1024)

// ---------------- helpers ----------------
__device__ __forceinline__ float sigmoidf_(float x) { return 1.0f / (1.0f + expf(-x)); }
__device__ __forceinline__ float siluf_(float x)    { return x * sigmoidf_(x); }
__device__ __forceinline__ float geluf_(float x)    { return 0.5f * x * (1.0f + erff(x * 0.70710678118654752f)); }
__device__ __forceinline__ float softplusf_(float x){ return (x > 20.0f) ? x : log1pf(expf(x)); }
__device__ __forceinline__ float tf32r(float x) {
    uint32_t u;
    asm("cvt.rna.tf32.f32 %0, %1;" : "=r"(u) : "f"(x));
    return __uint_as_float(u);
}
__device__ __forceinline__ uint32_t smem_u32(const void* p) {
    uint32_t a;
    asm("{ .reg .u64 t; cvta.to.shared.u64 t, %1; cvt.u32.u64 %0, t; }" : "=r"(a) : "l"(p));
    return a;
}
__device__ __forceinline__ void cpa16(uint32_t dst, const void* src) {
    asm volatile("cp.async.cg.shared.global [%0], [%1], 16;" :: "r"(dst), "l"(src));
}

// ---------------- weight transpose + tf32 round: src[K,N] -> dst[N,K] ----------------
__global__ void transpose_round_kernel(const float* __restrict__ src, float* __restrict__ dst,
                                       int K, int N) {
    __shared__ float t[32][33];
    int kb = blockIdx.y * 32, nb = blockIdx.x * 32;
    int x = threadIdx.x, y = threadIdx.y;  // 32 x 8
    #pragma unroll
    for (int i = 0; i < 4; i++)
        t[y + 8 * i][x] = src[(size_t)(kb + y + 8 * i) * N + nb + x];
    __syncthreads();
    #pragma unroll
    for (int i = 0; i < 4; i++)
        dst[(size_t)(nb + y + 8 * i) * K + kb + x] = tf32r(t[x][y + 8 * i]);
}

// ---------------- tf32 mma.sync GEMM: C[M,N] = A[M,K] @ Bt[N,K]^T ----------------
// EPI: 0 none, 2 bias+gelu+round, 3 +res, 4 bias+res
#define SROW 36                       /* padded k-stride in floats */
#define STAGE_FLOATS (2 * 128 * SROW) /* A tile + B tile */
#define SMEM_DYN (3 * STAGE_FLOATS * 4)

template<int EPI>
__global__ void __launch_bounds__(256, 1)
gemm_mma(const float* __restrict__ A, const float* __restrict__ Bt, float* __restrict__ C,
         int M_, int N_, int K_, const float* __restrict__ bias, const float* __restrict__ res) {
    extern __shared__ float sm[];
    int tid = threadIdx.x, wid = tid >> 5, lane = tid & 31;
    int g = lane >> 2, tg = lane & 3;
    int bm = blockIdx.y * 128, bn = blockIdx.x * 128;
    int wm = (wid & 1) * 64, wn = (wid >> 1) * 32;

    // loaders: 256 threads, each row-half (16 floats = 4x cp.async16)
    int arow = tid >> 1, ah = (tid & 1) * 16;
    const float* gA = A + (size_t)(bm + arow) * K_ + ah;
    const float* gB = Bt + (size_t)(bn + arow) * K_ + ah;
    uint32_t sbase = smem_u32(sm);
    uint32_t sAoff = (arow * SROW + ah) * 4;
    uint32_t sBoff = sAoff + 128 * SROW * 4;

    auto load_stage = [&](int chunk, int stage) {
        uint32_t st = sbase + stage * STAGE_FLOATS * 4;
        const float* a = gA + chunk * 32;
        const float* b = gB + chunk * 32;
        #pragma unroll
        for (int i = 0; i < 4; i++) cpa16(st + sAoff + i * 16, a + i * 4);
        #pragma unroll
        for (int i = 0; i < 4; i++) cpa16(st + sBoff + i * 16, b + i * 4);
        asm volatile("cp.async.commit_group;" ::: "memory");
    };

    float acc[4][4][4];
    #pragma unroll
    for (int i = 0; i < 4; i++)
        #pragma unroll
        for (int j = 0; j < 4; j++)
            #pragma unroll
            for (int r = 0; r < 4; r++) acc[i][j][r] = 0.f;

    const int NK = K_ >> 5;
    load_stage(0, 0);
    load_stage(1, 1);

    for (int k = 0; k < NK; k++) {
        int sk = k - (k / 3) * 3;
        asm volatile("cp.async.wait_group %0;" :: "n"(1) : "memory");
        __syncthreads();
        const float* As = sm + sk * STAGE_FLOATS;
        const float* Bs = As + 128 * SROW;

        #pragma unroll
        for (int kk = 0; kk < 32; kk += 8) {
            uint32_t af[4][4], bf[4][2];
            #pragma unroll
            for (int mt = 0; mt < 4; mt++) {
                const float* p = As + (wm + mt * 16 + g) * SROW + kk + tg;
                af[mt][0] = __float_as_uint(p[0]);
                af[mt][1] = __float_as_uint(p[8 * SROW]);
                af[mt][2] = __float_as_uint(p[4]);
                af[mt][3] = __float_as_uint(p[8 * SROW + 4]);
            }
            #pragma unroll
            for (int nt = 0; nt < 4; nt++) {
                const float* p = Bs + (wn + nt * 8 + g) * SROW + kk + tg;
                bf[nt][0] = __float_as_uint(p[0]);
                bf[nt][1] = __float_as_uint(p[4]);
            }
            #pragma unroll
            for (int mt = 0; mt < 4; mt++)
                #pragma unroll
                for (int nt = 0; nt < 4; nt++)
                    asm volatile(
                        "mma.sync.aligned.m16n8k8.row.col.f32.tf32.tf32.f32 "
                        "{%0,%1,%2,%3}, {%4,%5,%6,%7}, {%8,%9}, {%0,%1,%2,%3};"
                        : "+f"(acc[mt][nt][0]), "+f"(acc[mt][nt][1]),
                          "+f"(acc[mt][nt][2]), "+f"(acc[mt][nt][3])
                        : "r"(af[mt][0]), "r"(af[mt][1]), "r"(af[mt][2]), "r"(af[mt][3]),
                          "r"(bf[nt][0]), "r"(bf[nt][1]));
        }
        __syncthreads();
        if (k + 2 < NK) load_stage(k + 2, (k + 2) - ((k + 2) / 3) * 3);
        else asm volatile("cp.async.commit_group;" ::: "memory");
    }

    // epilogue: direct float2 stores from fragment layout
    #pragma unroll
    for (int mt = 0; mt < 4; mt++) {
        #pragma unroll
        for (int nt = 0; nt < 4; nt++) {
            int col = bn + wn + nt * 8 + 2 * tg;
            float b0 = 0.f, b1 = 0.f;
            if (EPI == 2 || EPI == 4) { b0 = bias[col]; b1 = bias[col + 1]; }
            #pragma unroll
            for (int h2 = 0; h2 < 2; h2++) {
                int row = bm + wm + mt * 16 + g + h2 * 8;
                float v0 = acc[mt][nt][2 * h2], v1 = acc[mt][nt][2 * h2 + 1];
                if (EPI == 2 || EPI == 4) { v0 += b0; v1 += b1; }
                if (EPI == 2) { v0 = tf32r(geluf_(v0)); v1 = tf32r(geluf_(v1)); }
                if (EPI == 3 || EPI == 4) {
                    float2 rr = *(const float2*)(res + (size_t)row * N_ + col);
                    v0 += rr.x; v1 += rr.y;
                }
                float2 o2; o2.x = v0; o2.y = v1;
                *(float2*)(C + (size_t)row * N_ + col) = o2;
            }
        }
    }
}

// ---------------- LayerNorm (tf32-rounded output) ----------------
__global__ void ln_kernel(const float* __restrict__ x, const float* __restrict__ w,
                          const float* __restrict__ b, float* __restrict__ out) {
    int row = blockIdx.x;
    const float* xr = x + (size_t)row * Dd;
    float s1 = 0.f, s2 = 0.f;
    float vals[4];
    #pragma unroll
    for (int i = 0; i < 4; i++) {
        float v = xr[threadIdx.x + i * 256];
        vals[i] = v; s1 += v; s2 += v * v;
    }
    __shared__ float sh[2][8];
    int lane = threadIdx.x & 31, wid = threadIdx.x >> 5;
    #pragma unroll
    for (int off = 16; off > 0; off >>= 1) {
        s1 += __shfl_xor_sync(0xffffffffu, s1, off);
        s2 += __shfl_xor_sync(0xffffffffu, s2, off);
    }
    if (lane == 0) { sh[0][wid] = s1; sh[1][wid] = s2; }
    __syncthreads();
    if (threadIdx.x == 0) {
        float a = 0.f, c = 0.f;
        #pragma unroll
        for (int i = 0; i < 8; i++) { a += sh[0][i]; c += sh[1][i]; }
        sh[0][0] = a; sh[1][0] = c;
    }
    __syncthreads();
    float mean = sh[0][0] * (1.0f / Dd);
    float var  = sh[1][0] * (1.0f / Dd) - mean * mean;
    float inv  = rsqrtf(var + 1e-5f);
    #pragma unroll
    for (int i = 0; i < 4; i++) {
        int c = threadIdx.x + i * 256;
        out[(size_t)row * Dd + c] = tf32r((vals[i] - mean) * inv * w[c] + b[c]);
    }
}

// ---------------- g / beta small projections ----------------
__global__ void gbeta_kernel(const float* __restrict__ normed, const float* __restrict__ Wa,
                             const float* __restrict__ Wb, const float* __restrict__ A_log,
                             const float* __restrict__ dt_bias, float* __restrict__ g,
                             float* __restrict__ beta) {
    int row = blockIdx.x * 8 + (threadIdx.x >> 5);
    int lane = threadIdx.x & 31;
    const float* xr = normed + (size_t)row * Dd;
    float acc[8];
    #pragma unroll
    for (int j = 0; j < 8; j++) acc[j] = 0.f;
    for (int k = lane; k < Dd; k += 32) {
        float xv = xr[k];
        const float* wa = Wa + k * 4;
        const float* wb = Wb + k * 4;
        #pragma unroll
        for (int j = 0; j < 4; j++) { acc[j] += xv * wa[j]; acc[4 + j] += xv * wb[j]; }
    }
    #pragma unroll
    for (int off = 16; off > 0; off >>= 1)
        #pragma unroll
        for (int j = 0; j < 8; j++) acc[j] += __shfl_xor_sync(0xffffffffu, acc[j], off);
    if (lane < 4) {
        float xa = acc[lane] + dt_bias[lane];
        g[row * 4 + lane] = -expf(A_log[lane]) * softplusf_(xa);
        beta[row * 4 + lane] = sigmoidf_(acc[4 + lane]);
    }
}

// ---------------- causal depthwise conv (K=4) + SiLU ----------------
__global__ void conv_silu_kernel(const float* __restrict__ x, const float* __restrict__ w,
                                 float* __restrict__ y, int C, long total) {
    long idx = (long)blockIdx.x * blockDim.x + threadIdx.x;
    if (idx >= total) return;
    int c = (int)(idx % C);
    long bt = idx / C;
    int t = (int)(bt % Tt);
    long bbase = (bt / Tt) * Tt;
    const float* w4 = w + c * 4;
    float acc = 0.f;
    #pragma unroll
    for (int i = 0; i < 4; i++) {
        int tt = t - 3 + i;
        if (tt >= 0) acc += x[(bbase + tt) * C + c] * w4[i];
    }
    y[idx] = siluf_(acc);
}

// ---------------- l2norm over DK=256 ----------------
__global__ void l2norm_kernel(float* __restrict__ x, float extra_scale) {
    int rowh = blockIdx.x;
    float* p = x + (size_t)rowh * DKk;
    float v = p[threadIdx.x];
    float ss = v * v;
    __shared__ float sh[8];
    int lane = threadIdx.x & 31, wid = threadIdx.x >> 5;
    #pragma unroll
    for (int off = 16; off > 0; off >>= 1) ss += __shfl_xor_sync(0xffffffffu, ss, off);
    if (lane == 0) sh[wid] = ss;
    __syncthreads();
    if (threadIdx.x == 0) {
        float a = 0.f;
        #pragma unroll
        for (int i = 0; i < 8; i++) a += sh[i];
        sh[0] = a;
    }
    __syncthreads();
    p[threadIdx.x] = v * rsqrtf(sh[0] + 1e-6f) * extra_scale;
}

// ---------------- gated delta rule scan ----------------
__global__ void __launch_bounds__(256)
scan_kernel(const float* __restrict__ q, const float* __restrict__ k, const float* __restrict__ v,
            const float* __restrict__ g, const float* __restrict__ beta, float* __restrict__ o) {
    int b  = blockIdx.x >> 5;
    int h  = (blockIdx.x >> 3) & 3;
    int sl = blockIdx.x & 7;
    int v0 = sl * 64;
    int tid = threadIdx.x;
    int kb = tid & 3, vi = tid >> 2;

    __shared__ float qs[256], ks[256], vs[64], sgb[2];
    float S[64];
    #pragma unroll
    for (int j = 0; j < 64; j++) S[j] = 0.f;
    float kreg[64];

    for (int t = 0; t < Tt; t++) {
        long row = (long)b * Tt + t;
        qs[tid] = q[row * KDIM + h * DKk + tid];
        ks[tid] = k[row * KDIM + h * DKk + tid];
        if (tid < 64) vs[tid] = v[row * VDIM + h * DVv + v0 + tid];
        if (tid == 0) { sgb[0] = expf(g[row * Hh + h]); sgb[1] = beta[row * Hh + h]; }
        __syncthreads();
        float eg = sgb[0], bt = sgb[1];

        float partial = 0.f;
        #pragma unroll
        for (int j = 0; j < 64; j++) {
            float kv = ks[kb + 4 * j];
            kreg[j] = kv;
            partial += kv * S[j];
        }
        partial += __shfl_xor_sync(0xffffffffu, partial, 1);
        partial += __shfl_xor_sync(0xffffffffu, partial, 2);
        float delta = (vs[vi] - eg * partial) * bt;

        float opart = 0.f;
        #pragma unroll
        for (int j = 0; j < 64; j++) {
            float sv = eg * S[j] + kreg[j] * delta;
            S[j] = sv;
            opart += qs[kb + 4 * j] * sv;
        }
        opart += __shfl_xor_sync(0xffffffffu, opart, 1);
        opart += __shfl_xor_sync(0xffffffffu, opart, 2);
        if (kb == 0) o[row * VDIM + h * DVv + v0 + vi] = opart;
        __syncthreads();
    }
}

// ---------------- gated RMSNorm + silu(gate), tf32-rounded ----------------
__global__ void rmsgate_kernel(float* __restrict__ o, const float* __restrict__ gate,
                               const float* __restrict__ onw) {
    int rowh = blockIdx.x;
    long row = rowh >> 2;
    int h = rowh & 3;
    float* op = o + row * VDIM + h * DVv;
    const float* gp = gate + row * VDIM + h * DVv;
    float v1 = op[threadIdx.x], v2 = op[threadIdx.x + 256];
    float ss = v1 * v1 + v2 * v2;
    __shared__ float sh[8];
    int lane = threadIdx.x & 31, wid = threadIdx.x >> 5;
    #pragma unroll
    for (int off = 16; off > 0; off >>= 1) ss += __shfl_xor_sync(0xffffffffu, ss, off);
    if (lane == 0) sh[wid] = ss;
    __syncthreads();
    if (threadIdx.x == 0) {
        float a = 0.f;
        #pragma unroll
        for (int i = 0; i < 8; i++) a += sh[i];
        sh[0] = a;
    }
    __syncthreads();
    float scale = rsqrtf(sh[0] * (1.0f / DVv) + 1e-5f);
    int c1 = threadIdx.x, c2 = threadIdx.x + 256;
    op[c1] = tf32r(v1 * scale * onw[c1] * siluf_(gp[c1]));
    op[c2] = tf32r(v2 * scale * onw[c2] * siluf_(gp[c2]));
}

// ---------------- launcher ----------------
extern "C" void kernel_launch(void* const* d_in, const int* in_sizes, int n_in,
                              void* d_out, int out_size) {
    const float* x        = (const float*)d_in[0];
    const float* Wq       = (const float*)d_in[1];
    const float* Wk       = (const float*)d_in[2];
    const float* Wv       = (const float*)d_in[3];
    const float* Wa       = (const float*)d_in[4];
    const float* Wb       = (const float*)d_in[5];
    const float* Wg       = (const float*)d_in[6];
    const float* conv_q_w = (const float*)d_in[7];
    const float* conv_k_w = (const float*)d_in[8];
    const float* conv_v_w = (const float*)d_in[9];
    const float* A_log    = (const float*)d_in[10];
    const float* dt_bias  = (const float*)d_in[11];
    const float* o_norm_w = (const float*)d_in[12];
    const float* Wo       = (const float*)d_in[13];
    const float* ln1_w    = (const float*)d_in[14];
    const float* ln1_b    = (const float*)d_in[15];
    const float* ln2_w    = (const float*)d_in[16];
    const float* ln2_b    = (const float*)d_in[17];
    const float* ffn_w1   = (const float*)d_in[18];
    const float* ffn_b1   = (const float*)d_in[19];
    const float* ffn_w2   = (const float*)d_in[20];
    const float* ffn_b2   = (const float*)d_in[21];
    float* out = (float*)d_out;

    float *normed, *xq, *xk, *xv, *q, *k, *v, *gate, *gg, *bb, *o, *x2, *hbuf, *ffn1, *wt;
    cudaGetSymbolAddress((void**)&normed, g_normed);
    cudaGetSymbolAddress((void**)&xq, g_xq);
    cudaGetSymbolAddress((void**)&xk, g_xk);
    cudaGetSymbolAddress((void**)&xv, g_xv);
    cudaGetSymbolAddress((void**)&q, g_q);
    cudaGetSymbolAddress((void**)&k, g_k);
    cudaGetSymbolAddress((void**)&v, g_v);
    cudaGetSymbolAddress((void**)&gate, g_gate);
    cudaGetSymbolAddress((void**)&gg, g_gg);
    cudaGetSymbolAddress((void**)&bb, g_bb);
    cudaGetSymbolAddress((void**)&o, g_o);
    cudaGetSymbolAddress((void**)&x2, g_x2);
    cudaGetSymbolAddress((void**)&hbuf, g_hbuf);
    cudaGetSymbolAddress((void**)&ffn1, g_ffn1);
    cudaGetSymbolAddress((void**)&wt, g_wt);

    cudaFuncSetAttribute(gemm_mma<0>, cudaFuncAttributeMaxDynamicSharedMemorySize, SMEM_DYN);
    cudaFuncSetAttribute(gemm_mma<2>, cudaFuncAttributeMaxDynamicSharedMemorySize, SMEM_DYN);
    cudaFuncSetAttribute(gemm_mma<3>, cudaFuncAttributeMaxDynamicSharedMemorySize, SMEM_DYN);
    cudaFuncSetAttribute(gemm_mma<4>, cudaFuncAttributeMaxDynamicSharedMemorySize, SMEM_DYN);

    // 0. weight transposes (+tf32 round)
    {
        dim3 blk(32, 8);
        transpose_round_kernel<<<dim3(KDIM/32, Dd/32),  blk>>>(Wq,     wt + WT_Q,  Dd,   KDIM);
        transpose_round_kernel<<<dim3(KDIM/32, Dd/32),  blk>>>(Wk,     wt + WT_K,  Dd,   KDIM);
        transpose_round_kernel<<<dim3(VDIM/32, Dd/32),  blk>>>(Wv,     wt + WT_V,  Dd,   VDIM);
        transpose_round_kernel<<<dim3(VDIM/32, Dd/32),  blk>>>(Wg,     wt + WT_G,  Dd,   VDIM);
        transpose_round_kernel<<<dim3(Dd/32,   VDIM/32),blk>>>(Wo,     wt + WT_O,  VDIM, Dd);
        transpose_round_kernel<<<dim3(FFND/32, Dd/32),  blk>>>(ffn_w1, wt + WT_F1, Dd,   FFND);
        transpose_round_kernel<<<dim3(Dd/32,   FFND/32),blk>>>(ffn_w2, wt + WT_F2, FFND, Dd);
    }

    // 1. LayerNorm 1
    ln_kernel<<<NROWS, 256>>>(x, ln1_w, ln1_b, normed);

    // 2. projections (tensor cores via mma.sync tf32)
    gemm_mma<0><<<dim3(KDIM/128, NROWS/128), 256, SMEM_DYN>>>(normed, wt + WT_Q, xq, NROWS, KDIM, Dd, nullptr, nullptr);
    gemm_mma<0><<<dim3(KDIM/128, NROWS/128), 256, SMEM_DYN>>>(normed, wt + WT_K, xk, NROWS, KDIM, Dd, nullptr, nullptr);
    gemm_mma<0><<<dim3(VDIM/128, NROWS/128), 256, SMEM_DYN>>>(normed, wt + WT_V, xv, NROWS, VDIM, Dd, nullptr, nullptr);
    gemm_mma<0><<<dim3(VDIM/128, NROWS/128), 256, SMEM_DYN>>>(normed, wt + WT_G, gate, NROWS, VDIM, Dd, nullptr, nullptr);
    gbeta_kernel<<<NROWS / 8, 256>>>(normed, Wa, Wb, A_log, dt_bias, gg, bb);

    // 3. conv + silu
    {
        long tq = (long)NROWS * KDIM;
        conv_silu_kernel<<<(unsigned)((tq + 255) / 256), 256>>>(xq, conv_q_w, q, KDIM, tq);
        conv_silu_kernel<<<(unsigned)((tq + 255) / 256), 256>>>(xk, conv_k_w, k, KDIM, tq);
        long tv = (long)NROWS * VDIM;
        conv_silu_kernel<<<(unsigned)((tv + 255) / 256), 256>>>(xv, conv_v_w, v, VDIM, tv);
    }

    // 4. l2norm
    l2norm_kernel<<<NROWS * Hh, 256>>>(q, 0.0625f);
    l2norm_kernel<<<NROWS * Hh, 256>>>(k, 1.0f);

    // 5. scan
    scan_kernel<<<Bb * Hh * 8, 256>>>(q, k, v, gg, bb, o);

    // 6. gated RMSNorm
    rmsgate_kernel<<<NROWS * Hh, 256>>>(o, gate, o_norm_w);

    // 7. x2 = x + o @ Wo
    gemm_mma<3><<<dim3(Dd/128, NROWS/128), 256, SMEM_DYN>>>(o, wt + WT_O, x2, NROWS, Dd, VDIM, nullptr, x);

    // 8. LN2 + FFN
    ln_kernel<<<NROWS, 256>>>(x2, ln2_w, ln2_b, hbuf);
    gemm_mma<2><<<dim3(FFND/128, NROWS/128), 256, SMEM_DYN>>>(hbuf, wt + WT_F1, ffn1, NROWS, FFND, Dd, ffn_b1, nullptr);
    gemm_mma<4><<<dim3(Dd/128, NROWS/128), 256, SMEM_DYN>>>(ffn1, wt + WT_F2, out, NROWS, Dd, FFND, ffn_b2, x2);
}

// round 4
// speedup vs baseline: 2.0427x; 1.2756x over previous
#include <cuda_runtime.h>
#include <cuda_fp16.h>
#include <math.h>
#include <stdint.h>

#define Bb   4
#define Tt   2048
#define Dd   1024
#define Hh   4
#define DKk  256
#define DVv  512
#define KDIM 1024
#define VDIM 2048
#define FFND 4096
#define NROWS (Bb*Tt)   /* 8192 */
#define NQKVG 6144      /* fused Q|K|V|G output columns */

// ---------------- scratch ----------------
__device__ __half  g_normh[NROWS*Dd];
__device__ float   g_xall[(size_t)NROWS*NQKVG];
__device__ float   g_q[NROWS*KDIM];
__device__ float   g_k[NROWS*KDIM];
__device__ float   g_v[NROWS*VDIM];
__device__ float   g_gg[NROWS*Hh];
__device__ float   g_bb[NROWS*Hh];
__device__ float   g_o[NROWS*VDIM];
__device__ __half  g_oh[NROWS*VDIM];
__device__ float   g_x2[NROWS*Dd];
__device__ __half  g_hbufh[NROWS*Dd];
__device__ __half  g_ffn1h[(size_t)NROWS*FFND];
__device__ __half  g_wth[16*1024*1024];
#define WT_QKVG 0                 /* [6144][1024]: Q,K,V,G stacked */
#define WT_O   (6*1024*1024)      /* [1024][2048] */
#define WT_F1  (8*1024*1024)      /* [4096][1024] */
#define WT_F2  (12*1024*1024)     /* [1024][4096] */

// ---------------- helpers ----------------
__device__ __forceinline__ float sigmoidf_(float x) { return 1.0f / (1.0f + expf(-x)); }
__device__ __forceinline__ float siluf_(float x)    { return x * sigmoidf_(x); }
__device__ __forceinline__ float geluf_(float x)    { return 0.5f * x * (1.0f + erff(x * 0.70710678118654752f)); }
__device__ __forceinline__ float softplusf_(float x){ return (x > 20.0f) ? x : log1pf(expf(x)); }
__device__ __forceinline__ uint32_t smem_u32(const void* p) {
    uint32_t a;
    asm("{ .reg .u64 t; cvta.to.shared.u64 t, %1; cvt.u32.u64 %0, t; }" : "=r"(a) : "l"(p));
    return a;
}
__device__ __forceinline__ void cpa16(uint32_t dst, const void* src) {
    asm volatile("cp.async.cg.shared.global [%0], [%1], 16;" :: "r"(dst), "l"(src));
}
__device__ __forceinline__ void ldm4(uint32_t* r, uint32_t addr) {
    asm volatile("ldmatrix.sync.aligned.m8n8.x4.shared.b16 {%0,%1,%2,%3}, [%4];"
        : "=r"(r[0]), "=r"(r[1]), "=r"(r[2]), "=r"(r[3]) : "r"(addr));
}
#define SWZ(o) ((o) ^ (((o) >> 3) & 0x70))
__device__ __forceinline__ void stv(float* p, float v)  { *p = v; }
__device__ __forceinline__ void stv(__half* p, float v) { *p = __float2half(v); }

// ---------------- weight transpose + fp16: src[K,N] -> dst[N,K] ----------------
__global__ void transpose_h_kernel(const float* __restrict__ src, __half* __restrict__ dst,
                                   int K, int N) {
    __shared__ float t[32][33];
    int kb = blockIdx.y * 32, nb = blockIdx.x * 32;
    int x = threadIdx.x, y = threadIdx.y;  // 32 x 8
    #pragma unroll
    for (int i = 0; i < 4; i++)
        t[y + 8 * i][x] = src[(size_t)(kb + y + 8 * i) * N + nb + x];
    __syncthreads();
    #pragma unroll
    for (int i = 0; i < 4; i++)
        dst[(size_t)(nb + y + 8 * i) * K + kb + x] = __float2half(t[x][y + 8 * i]);
}

// ---------------- fp16 mma.sync GEMM: C[M,N] = A[M,K] @ Bt[N,K]^T ----------------
// EPI: 0 float none | 2 half bias+gelu | 3 float +res | 4 float bias+res
#define STG_BYTES 32768           /* A 128x128B + B 128x128B */
#define SMEM_DYN (3 * STG_BYTES)

template<int EPI>
__global__ void __launch_bounds__(256, 1)
hgemm(const __half* __restrict__ A, const __half* __restrict__ Bt, void* __restrict__ Cv,
      int M_, int N_, int K_, const float* __restrict__ bias, const float* __restrict__ res) {
    extern __shared__ char sm[];
    uint32_t sbase = smem_u32(sm);
    int tid = threadIdx.x, wid = tid >> 5, lane = tid & 31;
    int g = lane >> 2, tg = lane & 3;
    int bm = blockIdx.y * 128, bn = blockIdx.x * 128;
    int wm = (wid & 1) * 64, wn = (wid >> 1) * 32;

    // ---- loaders: thread t loads 4x16B for A tile and 4x16B for B tile
    int lrow = tid >> 1, lc0 = (tid & 1) * 4;
    const __half* gA = A + (size_t)(bm + lrow) * K_ + lc0 * 8;
    const __half* gB = Bt + (size_t)(bn + lrow) * K_ + lc0 * 8;
    uint32_t sAo[4], sBo[4];
    #pragma unroll
    for (int i = 0; i < 4; i++) {
        uint32_t off = lrow * 128 + (lc0 + i) * 16;
        sAo[i] = SWZ(off);
        sBo[i] = 16384 + SWZ(off);
    }
    auto load_stage = [&](int chunk, int stage) {
        uint32_t st = sbase + stage * STG_BYTES;
        const __half* a = gA + chunk * 64;
        const __half* b = gB + chunk * 64;
        #pragma unroll
        for (int i = 0; i < 4; i++) cpa16(st + sAo[i], a + i * 8);
        #pragma unroll
        for (int i = 0; i < 4; i++) cpa16(st + sBo[i], b + i * 8);
        asm volatile("cp.async.commit_group;" ::: "memory");
    };

    // ---- ldmatrix lane address components
    int arow = lane & 15;
    int acb  = (lane >> 4) * 16;           // byte offset within 16-halves
    int bsel = lane >> 3;
    int brow = (lane & 7) + ((bsel & 2) ? 8 : 0);
    int bcb  = (bsel & 1) * 16;
    uint32_t aBase[4], bBase[2];
    #pragma unroll
    for (int mt = 0; mt < 4; mt++)
        aBase[mt] = (wm + mt * 16 + arow) * 128 + acb;
    #pragma unroll
    for (int np = 0; np < 2; np++)
        bBase[np] = 16384 + (wn + np * 16 + brow) * 128 + bcb;

    float acc[4][4][4];
    #pragma unroll
    for (int i = 0; i < 4; i++)
        #pragma unroll
        for (int j = 0; j < 4; j++)
            #pragma unroll
            for (int r = 0; r < 4; r++) acc[i][j][r] = 0.f;

    const int NK = K_ >> 6;  // chunks of 64 halves
    load_stage(0, 0);
    load_stage(1, 1);

    for (int k = 0; k < NK; k++) {
        int sk = k - (k / 3) * 3;
        asm volatile("cp.async.wait_group %0;" :: "n"(1) : "memory");
        __syncthreads();
        uint32_t st = sbase + sk * STG_BYTES;

        #pragma unroll
        for (int kk = 0; kk < 4; kk++) {
            int kbyte = kk * 32;
            uint32_t af[4][4], bf[4][2];
            #pragma unroll
            for (int mt = 0; mt < 4; mt++)
                ldm4(af[mt], st + SWZ(aBase[mt] + kbyte));
            #pragma unroll
            for (int np = 0; np < 2; np++) {
                uint32_t r4[4];
                ldm4(r4, st + SWZ(bBase[np] + kbyte));
                bf[2 * np][0] = r4[0]; bf[2 * np][1] = r4[1];
                bf[2 * np + 1][0] = r4[2]; bf[2 * np + 1][1] = r4[3];
            }
            #pragma unroll
            for (int mt = 0; mt < 4; mt++)
                #pragma unroll
                for (int nt = 0; nt < 4; nt++)
                    asm volatile(
                        "mma.sync.aligned.m16n8k16.row.col.f32.f16.f16.f32 "
                        "{%0,%1,%2,%3}, {%4,%5,%6,%7}, {%8,%9}, {%0,%1,%2,%3};"
                        : "+f"(acc[mt][nt][0]), "+f"(acc[mt][nt][1]),
                          "+f"(acc[mt][nt][2]), "+f"(acc[mt][nt][3])
                        : "r"(af[mt][0]), "r"(af[mt][1]), "r"(af[mt][2]), "r"(af[mt][3]),
                          "r"(bf[nt][0]), "r"(bf[nt][1]));
        }
        __syncthreads();
        if (k + 2 < NK) load_stage(k + 2, (k + 2) - ((k + 2) / 3) * 3);
        else asm volatile("cp.async.commit_group;" ::: "memory");
    }

    // ---- epilogue
    float* Cf = (float*)Cv;
    __half* Ch = (__half*)Cv;
    #pragma unroll
    for (int mt = 0; mt < 4; mt++) {
        #pragma unroll
        for (int nt = 0; nt < 4; nt++) {
            int col = bn + wn + nt * 8 + 2 * tg;
            float b0 = 0.f, b1 = 0.f;
            if (EPI == 2 || EPI == 4) { b0 = bias[col]; b1 = bias[col + 1]; }
            #pragma unroll
            for (int h2 = 0; h2 < 2; h2++) {
                int row = bm + wm + mt * 16 + g + h2 * 8;
                float v0 = acc[mt][nt][2 * h2], v1 = acc[mt][nt][2 * h2 + 1];
                if (EPI == 2 || EPI == 4) { v0 += b0; v1 += b1; }
                if (EPI == 2) {
                    __half2 hv;
                    hv.x = __float2half(geluf_(v0));
                    hv.y = __float2half(geluf_(v1));
                    *(__half2*)(Ch + (size_t)row * N_ + col) = hv;
                } else {
                    if (EPI == 3 || EPI == 4) {
                        float2 rr = *(const float2*)(res + (size_t)row * N_ + col);
                        v0 += rr.x; v1 += rr.y;
                    }
                    float2 o2; o2.x = v0; o2.y = v1;
                    *(float2*)(Cf + (size_t)row * N_ + col) = o2;
                }
            }
        }
    }
}

// ---------------- LayerNorm -> half output ----------------
__global__ void ln_kernel(const float* __restrict__ x, const float* __restrict__ w,
                          const float* __restrict__ b, __half* __restrict__ out) {
    int row = blockIdx.x;
    const float* xr = x + (size_t)row * Dd;
    float s1 = 0.f, s2 = 0.f;
    float vals[4];
    #pragma unroll
    for (int i = 0; i < 4; i++) {
        float v = xr[threadIdx.x + i * 256];
        vals[i] = v; s1 += v; s2 += v * v;
    }
    __shared__ float sh[2][8];
    int lane = threadIdx.x & 31, wid = threadIdx.x >> 5;
    #pragma unroll
    for (int off = 16; off > 0; off >>= 1) {
        s1 += __shfl_xor_sync(0xffffffffu, s1, off);
        s2 += __shfl_xor_sync(0xffffffffu, s2, off);
    }
    if (lane == 0) { sh[0][wid] = s1; sh[1][wid] = s2; }
    __syncthreads();
    if (threadIdx.x == 0) {
        float a = 0.f, c = 0.f;
        #pragma unroll
        for (int i = 0; i < 8; i++) { a += sh[0][i]; c += sh[1][i]; }
        sh[0][0] = a; sh[1][0] = c;
    }
    __syncthreads();
    float mean = sh[0][0] * (1.0f / Dd);
    float var  = sh[1][0] * (1.0f / Dd) - mean * mean;
    float inv  = rsqrtf(var + 1e-5f);
    #pragma unroll
    for (int i = 0; i < 4; i++) {
        int c = threadIdx.x + i * 256;
        out[(size_t)row * Dd + c] = __float2half((vals[i] - mean) * inv * w[c] + b[c]);
    }
}

// ---------------- g / beta small projections (reads half normed) ----------------
__global__ void gbeta_kernel(const __half* __restrict__ normed, const float* __restrict__ Wa,
                             const float* __restrict__ Wb, const float* __restrict__ A_log,
                             const float* __restrict__ dt_bias, float* __restrict__ g,
                             float* __restrict__ beta) {
    int row = blockIdx.x * 8 + (threadIdx.x >> 5);
    int lane = threadIdx.x & 31;
    const __half* xr = normed + (size_t)row * Dd;
    float acc[8];
    #pragma unroll
    for (int j = 0; j < 8; j++) acc[j] = 0.f;
    for (int k = lane; k < Dd; k += 32) {
        float xv = __half2float(xr[k]);
        const float* wa = Wa + k * 4;
        const float* wb = Wb + k * 4;
        #pragma unroll
        for (int j = 0; j < 4; j++) { acc[j] += xv * wa[j]; acc[4 + j] += xv * wb[j]; }
    }
    #pragma unroll
    for (int off = 16; off > 0; off >>= 1)
        #pragma unroll
        for (int j = 0; j < 8; j++) acc[j] += __shfl_xor_sync(0xffffffffu, acc[j], off);
    if (lane < 4) {
        float xa = acc[lane] + dt_bias[lane];
        g[row * 4 + lane] = -expf(A_log[lane]) * softplusf_(xa);
        beta[row * 4 + lane] = sigmoidf_(acc[4 + lane]);
    }
}

// ---------------- causal depthwise conv (K=4) + SiLU, strided input ----------------
__global__ void conv_silu_kernel(const float* __restrict__ x, int xstr,
                                 const float* __restrict__ w,
                                 float* __restrict__ y, int C, long total) {
    long idx = (long)blockIdx.x * blockDim.x + threadIdx.x;
    if (idx >= total) return;
    int c = (int)(idx % C);
    long bt = idx / C;
    int t = (int)(bt % Tt);
    long bbase = (bt / Tt) * Tt;
    const float* w4 = w + c * 4;
    float acc = 0.f;
    #pragma unroll
    for (int i = 0; i < 4; i++) {
        int tt = t - 3 + i;
        if (tt >= 0) acc += x[(bbase + tt) * (long)xstr + c] * w4[i];
    }
    y[idx] = siluf_(acc);
}

// ---------------- l2norm over DK=256 ----------------
__global__ void l2norm_kernel(float* __restrict__ x, float extra_scale) {
    int rowh = blockIdx.x;
    float* p = x + (size_t)rowh * DKk;
    float v = p[threadIdx.x];
    float ss = v * v;
    __shared__ float sh[8];
    int lane = threadIdx.x & 31, wid = threadIdx.x >> 5;
    #pragma unroll
    for (int off = 16; off > 0; off >>= 1) ss += __shfl_xor_sync(0xffffffffu, ss, off);
    if (lane == 0) sh[wid] = ss;
    __syncthreads();
    if (threadIdx.x == 0) {
        float a = 0.f;
        #pragma unroll
        for (int i = 0; i < 8; i++) a += sh[i];
        sh[0] = a;
    }
    __syncthreads();
    p[threadIdx.x] = v * rsqrtf(sh[0] + 1e-6f) * extra_scale;
}

// ---------------- gated delta rule scan (double-buffered smem) ----------------
__global__ void __launch_bounds__(256)
scan_kernel(const float* __restrict__ q, const float* __restrict__ k, const float* __restrict__ v,
            const float* __restrict__ g, const float* __restrict__ beta, float* __restrict__ o) {
    int b  = blockIdx.x >> 5;
    int h  = (blockIdx.x >> 3) & 3;
    int sl = blockIdx.x & 7;
    int v0 = sl * 64;
    int tid = threadIdx.x;
    int kb = tid & 3, vi = tid >> 2;

    __shared__ float qs[2][256], ks[2][256], vs[2][64], sgb[2][2];
    float S[64];
    #pragma unroll
    for (int j = 0; j < 64; j++) S[j] = 0.f;
    float kreg[64];

    for (int t = 0; t < Tt; t++) {
        int pb = t & 1;
        long row = (long)b * Tt + t;
        qs[pb][tid] = q[row * KDIM + h * DKk + tid];
        ks[pb][tid] = k[row * KDIM + h * DKk + tid];
        if (tid < 64) vs[pb][tid] = v[row * VDIM + h * DVv + v0 + tid];
        if (tid == 0) { sgb[pb][0] = expf(g[row * Hh + h]); sgb[pb][1] = beta[row * Hh + h]; }
        __syncthreads();
        float eg = sgb[pb][0], bt = sgb[pb][1];

        float partial = 0.f;
        #pragma unroll
        for (int j = 0; j < 64; j++) {
            float kv = ks[pb][kb + 4 * j];
            kreg[j] = kv;
            partial += kv * S[j];
        }
        partial += __shfl_xor_sync(0xffffffffu, partial, 1);
        partial += __shfl_xor_sync(0xffffffffu, partial, 2);
        float delta = (vs[pb][vi] - eg * partial) * bt;

        float opart = 0.f;
        #pragma unroll
        for (int j = 0; j < 64; j++) {
            float sv = eg * S[j] + kreg[j] * delta;
            S[j] = sv;
            opart += qs[pb][kb + 4 * j] * sv;
        }
        opart += __shfl_xor_sync(0xffffffffu, opart, 1);
        opart += __shfl_xor_sync(0xffffffffu, opart, 2);
        if (kb == 0) o[row * VDIM + h * DVv + v0 + vi] = opart;
    }
}

// ---------------- gated RMSNorm + silu(gate) -> half ----------------
__global__ void rmsgate_kernel(const float* __restrict__ o, const float* __restrict__ xall,
                               const float* __restrict__ onw, __half* __restrict__ oh) {
    int rowh = blockIdx.x;
    long row = rowh >> 2;
    int h = rowh & 3;
    const float* op = o + row * VDIM + h * DVv;
    const float* gp = xall + row * (long)NQKVG + 4096 + h * DVv;
    __half* ohp = oh + row * VDIM + h * DVv;
    float v1 = op[threadIdx.x], v2 = op[threadIdx.x + 256];
    float ss = v1 * v1 + v2 * v2;
    __shared__ float sh[8];
    int lane = threadIdx.x & 31, wid = threadIdx.x >> 5;
    #pragma unroll
    for (int off = 16; off > 0; off >>= 1) ss += __shfl_xor_sync(0xffffffffu, ss, off);
    if (lane == 0) sh[wid] = ss;
    __syncthreads();
    if (threadIdx.x == 0) {
        float a = 0.f;
        #pragma unroll
        for (int i = 0; i < 8; i++) a += sh[i];
        sh[0] = a;
    }
    __syncthreads();
    float scale = rsqrtf(sh[0] * (1.0f / DVv) + 1e-5f);
    int c1 = threadIdx.x, c2 = threadIdx.x + 256;
    ohp[c1] = __float2half(v1 * scale * onw[c1] * siluf_(gp[c1]));
    ohp[c2] = __float2half(v2 * scale * onw[c2] * siluf_(gp[c2]));
}

// ---------------- launcher ----------------
extern "C" void kernel_launch(void* const* d_in, const int* in_sizes, int n_in,
                              void* d_out, int out_size) {
    const float* x        = (const float*)d_in[0];
    const float* Wq       = (const float*)d_in[1];
    const float* Wk       = (const float*)d_in[2];
    const float* Wv       = (const float*)d_in[3];
    const float* Wa       = (const float*)d_in[4];
    const float* Wb       = (const float*)d_in[5];
    const float* Wg       = (const float*)d_in[6];
    const float* conv_q_w = (const float*)d_in[7];
    const float* conv_k_w = (const float*)d_in[8];
    const float* conv_v_w = (const float*)d_in[9];
    const float* A_log    = (const float*)d_in[10];
    const float* dt_bias  = (const float*)d_in[11];
    const float* o_norm_w = (const float*)d_in[12];
    const float* Wo       = (const float*)d_in[13];
    const float* ln1_w    = (const float*)d_in[14];
    const float* ln1_b    = (const float*)d_in[15];
    const float* ln2_w    = (const float*)d_in[16];
    const float* ln2_b    = (const float*)d_in[17];
    const float* ffn_w1   = (const float*)d_in[18];
    const float* ffn_b1   = (const float*)d_in[19];
    const float* ffn_w2   = (const float*)d_in[20];
    const float* ffn_b2   = (const float*)d_in[21];
    float* out = (float*)d_out;

    __half *normh, *oh, *hbufh, *ffn1h, *wth;
    float *xall, *q, *k, *v, *gg, *bb, *o, *x2;
    cudaGetSymbolAddress((void**)&normh, g_normh);
    cudaGetSymbolAddress((void**)&xall, g_xall);
    cudaGetSymbolAddress((void**)&q, g_q);
    cudaGetSymbolAddress((void**)&k, g_k);
    cudaGetSymbolAddress((void**)&v, g_v);
    cudaGetSymbolAddress((void**)&gg, g_gg);
    cudaGetSymbolAddress((void**)&bb, g_bb);
    cudaGetSymbolAddress((void**)&o, g_o);
    cudaGetSymbolAddress((void**)&oh, g_oh);
    cudaGetSymbolAddress((void**)&x2, g_x2);
    cudaGetSymbolAddress((void**)&hbufh, g_hbufh);
    cudaGetSymbolAddress((void**)&ffn1h, g_ffn1h);
    cudaGetSymbolAddress((void**)&wth, g_wth);

    cudaFuncSetAttribute(hgemm<0>, cudaFuncAttributeMaxDynamicSharedMemorySize, SMEM_DYN);
    cudaFuncSetAttribute(hgemm<2>, cudaFuncAttributeMaxDynamicSharedMemorySize, SMEM_DYN);
    cudaFuncSetAttribute(hgemm<3>, cudaFuncAttributeMaxDynamicSharedMemorySize, SMEM_DYN);
    cudaFuncSetAttribute(hgemm<4>, cudaFuncAttributeMaxDynamicSharedMemorySize, SMEM_DYN);

    // 0. weight transposes -> half [N,K]
    {
        dim3 blk(32, 8);
        transpose_h_kernel<<<dim3(KDIM/32, Dd/32),  blk>>>(Wq,     wth + WT_QKVG,            Dd,   KDIM);
        transpose_h_kernel<<<dim3(KDIM/32, Dd/32),  blk>>>(Wk,     wth + WT_QKVG + 1024*1024, Dd,  KDIM);
        transpose_h_kernel<<<dim3(VDIM/32, Dd/32),  blk>>>(Wv,     wth + WT_QKVG + 2*1024*1024, Dd, VDIM);
        transpose_h_kernel<<<dim3(VDIM/32, Dd/32),  blk>>>(Wg,     wth + WT_QKVG + 4*1024*1024, Dd, VDIM);
        transpose_h_kernel<<<dim3(Dd/32,   VDIM/32),blk>>>(Wo,     wth + WT_O,  VDIM, Dd);
        transpose_h_kernel<<<dim3(FFND/32, Dd/32),  blk>>>(ffn_w1, wth + WT_F1, Dd,   FFND);
        transpose_h_kernel<<<dim3(Dd/32,   FFND/32),blk>>>(ffn_w2, wth + WT_F2, FFND, Dd);
    }

    // 1. LayerNorm 1 -> half
    ln_kernel<<<NROWS, 256>>>(x, ln1_w, ln1_b, normh);

    // 2. fused Q|K|V|G projection: [8192,6144] = normh @ wtQKVG^T
    hgemm<0><<<dim3(NQKVG/128, NROWS/128), 256, SMEM_DYN>>>(normh, wth + WT_QKVG, xall,
                                                            NROWS, NQKVG, Dd, nullptr, nullptr);
    gbeta_kernel<<<NROWS / 8, 256>>>(normh, Wa, Wb, A_log, dt_bias, gg, bb);

    // 3. conv + silu from fused buffer (strided)
    {
        long tq = (long)NROWS * KDIM;
        conv_silu_kernel<<<(unsigned)((tq + 255) / 256), 256>>>(xall,        NQKVG, conv_q_w, q, KDIM, tq);
        conv_silu_kernel<<<(unsigned)((tq + 255) / 256), 256>>>(xall + 1024, NQKVG, conv_k_w, k, KDIM, tq);
        long tv = (long)NROWS * VDIM;
        conv_silu_kernel<<<(unsigned)((tv + 255) / 256), 256>>>(xall + 2048, NQKVG, conv_v_w, v, VDIM, tv);
    }

    // 4. l2norm
    l2norm_kernel<<<NROWS * Hh, 256>>>(q, 0.0625f);
    l2norm_kernel<<<NROWS * Hh, 256>>>(k, 1.0f);

    // 5. scan
    scan_kernel<<<Bb * Hh * 8, 256>>>(q, k, v, gg, bb, o);

    // 6. gated RMSNorm -> half
    rmsgate_kernel<<<NROWS * Hh, 256>>>(o, xall, o_norm_w, oh);

    // 7. x2 = x + oh @ WoT
    hgemm<3><<<dim3(Dd/128, NROWS/128), 256, SMEM_DYN>>>(oh, wth + WT_O, x2,
                                                         NROWS, Dd, VDIM, nullptr, x);

    // 8. LN2 + FFN
    ln_kernel<<<NROWS, 256>>>(x2, ln2_w, ln2_b, hbufh);
    hgemm<2><<<dim3(FFND/128, NROWS/128), 256, SMEM_DYN>>>(hbufh, wth + WT_F1, ffn1h,
                                                           NROWS, FFND, Dd, ffn_b1, nullptr);
    hgemm<4><<<dim3(Dd/128, NROWS/128), 256, SMEM_DYN>>>(ffn1h, wth + WT_F2, out,
                                                         NROWS, Dd, FFND, ffn_b2, x2);
}